// round 15
// baseline (speedup 1.0000x reference)
#include <cuda_runtime.h>
#include <cuda_bf16.h>
#include <math.h>

// Problem shape (fixed by setup_inputs)
#define N     2048
#define C     256
#define NCLS  8
#define KSEL  20
#define MAXC  384      // class size bound; tiles cover 6*64=384
#define EPS   1e-6f

typedef unsigned long long u64;

// Scratch (static __device__ — no allocations)
// g_D layout: [4 channel-quarters][N rows (original index)][MAXC positions]
__device__ float g_D[4ull * N * MAXC];
__device__ int   g_orderC[NCLS * MAXC];   // per-class member lists (original indices)
__device__ int   g_cntC[NCLS];
__device__ float g_partial[512];
__device__ unsigned int g_counter;

// triangle tile enumeration: x >= y, 6x6 -> 21 tiles
__device__ __constant__ int c_tx[21] = {0,1,1,2,2,2,3,3,3,3,4,4,4,4,4,5,5,5,5,5,5};
__device__ __constant__ int c_ty[21] = {0,0,1,0,1,2,0,1,2,3,0,1,2,3,4,0,1,2,3,4,5};

__device__ __forceinline__ float finf() { return __int_as_float(0x7f800000); }

__device__ __forceinline__ u64 addx2(u64 a, u64 b) {
    u64 r;
    asm("add.rn.f32x2 %0, %1, %2;" : "=l"(r) : "l"(a), "l"(b));
    return r;
}

// ---------------------------------------------------------------------------
// Kernel 1: class-blocked pairwise L1 (no eps -> symmetric), channel-quarter
// split, TRIANGLE tiles only (x >= y), mirror store via smem transpose.
// Unchanged from R14 (measured ~18us).
// ---------------------------------------------------------------------------
#define TB 64
#define KC 64      // channels per chunk == quarter size (32 packed pairs)
#define PADTB 66   // padded row length (528 bytes, multiple of 16)

__global__ __launch_bounds__(256, 3)
void dist_kernel(const float* __restrict__ feat, const int* __restrict__ target) {
    int bid = blockIdx.x;
    if (bid == 0 && threadIdx.x == 0) g_counter = 0u;   // reset for topk

    int cs  = bid / 168;               // channel quarter 0..3
    int b   = bid - cs * 168;
    int cls = b / 21;
    int e   = b - cls * 21;
    int x = c_tx[e], y = c_ty[e];      // x >= y

    __shared__ __align__(16) float As2[KC / 2][PADTB][2];   // a, pair packed
    __shared__ __align__(16) float Bs2[KC / 2][PADTB][2];   // -b, pair packed
    __shared__ __align__(16) int   list[MAXC];
    __shared__ int   s_wofs[8];
    __shared__ int   s_cnt;

    int t    = threadIdx.x;
    int lane = t & 31;
    int w    = t >> 5;

    // ---- cheap count first: early-exit for non-working tiles ----
    int4 t0 = *(const int4*)(target + t * 8);
    int4 t1 = *(const int4*)(target + t * 8 + 4);
    int tg[8] = {t0.x, t0.y, t0.z, t0.w, t1.x, t1.y, t1.z, t1.w};
    int mcount = 0;
#pragma unroll
    for (int u = 0; u < 8; u++) mcount += (tg[u] == cls);

    int red = mcount;
#pragma unroll
    for (int o = 16; o > 0; o >>= 1) red += __shfl_down_sync(0xffffffffu, red, o);
    if (lane == 0) s_wofs[w] = red;
    __syncthreads();
    if (t == 0) {
        int acc = 0;
#pragma unroll
        for (int ww = 0; ww < 8; ww++) acc += s_wofs[ww];
        s_cnt = acc;
    }
    __syncthreads();
    int cnt = min(s_cnt, MAXC);

    int ti0 = y * TB;
    int tj0 = x * TB;
    if (ti0 >= cnt || tj0 >= cnt) return;   // publishers (e==0) always pass

    // ---- full stable compaction (working blocks only) ----
    int incl = mcount;
#pragma unroll
    for (int o = 1; o < 32; o <<= 1) {
        int v = __shfl_up_sync(0xffffffffu, incl, o);
        if (lane >= o) incl += v;
    }
    if (lane == 31) s_wofs[w] = incl;
    __syncthreads();
    if (t == 0) {
        int acc = 0;
#pragma unroll
        for (int ww = 0; ww < 8; ww++) { int v = s_wofs[ww]; s_wofs[ww] = acc; acc += v; }
    }
    __syncthreads();
    int base = s_wofs[w] + incl - mcount;   // exclusive prefix for this thread
#pragma unroll
    for (int u = 0; u < 8; u++) {
        if (tg[u] == cls && base < MAXC) { list[base] = t * 8 + u; base++; }
    }
    __syncthreads();
    for (int p = cnt + t; p < MAXC; p += 256) list[p] = 0;   // safe padding
    __syncthreads();

    // publisher blocks export the list for topk (one block per class)
    if (cs == 0 && e == 0) {
        if (t == 0) g_cntC[cls] = cnt;
        for (int p = t; p < MAXC; p += 256) g_orderC[cls * MAXC + p] = list[p];
    }

    // ---- staging: thread t fills column lr, 16 channels ----
    {
        int lr = t & 63;
        int lc = (t >> 6) * 16;       // 0,16,32,48
        int gi = ti0 + lr, gj = tj0 + lr;
        const float* arow = feat + (size_t)list[min(gi, MAXC - 1)] * C;
        const float* brow = feat + (size_t)list[min(gj, MAXC - 1)] * C;
        int cc = cs * 64 + lc;
        int p0 = lc >> 1;
#pragma unroll
        for (int q = 0; q < 4; q++) {
            float4 pa = *(const float4*)(arow + cc + q * 4);
            float4 pb = *(const float4*)(brow + cc + q * 4);
            *(float2*)&As2[p0 + 2 * q + 0][lr][0] = make_float2(pa.x, pa.y);
            *(float2*)&As2[p0 + 2 * q + 1][lr][0] = make_float2(pa.z, pa.w);
            *(float2*)&Bs2[p0 + 2 * q + 0][lr][0] = make_float2(-pb.x, -pb.y);
            *(float2*)&Bs2[p0 + 2 * q + 1][lr][0] = make_float2(-pb.z, -pb.w);
        }
    }
    __syncthreads();

    int tx = t & 15;      // j columns: {2tx, 2tx+1, 32+2tx, 32+2tx+1}
    int ty = t >> 4;      // i rows: ty*4 + ii

    u64 acc2[16];
#pragma unroll
    for (int q = 0; q < 16; q++) acc2[q] = 0ull;

#pragma unroll
    for (int kk2 = 0; kk2 < KC / 2; kk2++) {
        ulonglong2 aL = *(const ulonglong2*)&As2[kk2][ty * 4][0];
        ulonglong2 aH = *(const ulonglong2*)&As2[kk2][ty * 4 + 2][0];
        u64 a2[4] = {aL.x, aL.y, aH.x, aH.y};
        ulonglong2 bL = *(const ulonglong2*)&Bs2[kk2][2 * tx][0];
        ulonglong2 bH = *(const ulonglong2*)&Bs2[kk2][32 + 2 * tx][0];
        u64 b2[4] = {bL.x, bL.y, bH.x, bH.y};
#pragma unroll
        for (int ii = 0; ii < 4; ii++)
#pragma unroll
            for (int c = 0; c < 4; c++) {
                u64 d = addx2(a2[ii], b2[c]);           // a - b
                d &= 0x7FFFFFFF7FFFFFFFull;             // packed |.|
                acc2[ii * 4 + c] = addx2(acc2[ii * 4 + c], d);
            }
    }

    float res[4][4];
#pragma unroll
    for (int ii = 0; ii < 4; ii++)
#pragma unroll
        for (int c = 0; c < 4; c++) {
            u64 a = acc2[ii * 4 + c];
            float lo = __uint_as_float((unsigned)(a & 0xFFFFFFFFull));
            float hi = __uint_as_float((unsigned)(a >> 32));
            res[ii][c] = lo + hi;
        }

    float* dq = g_D + (size_t)cs * N * MAXC;

#pragma unroll
    for (int ii = 0; ii < 4; ii++) {
        int ti = ti0 + ty * 4 + ii;
        if (ti >= cnt) continue;
        float* dr = dq + (size_t)list[ti] * MAXC + tj0;
        float o0 = (ti == tj0 + 2 * tx)          ? finf() : res[ii][0];
        float o1 = (ti == tj0 + 2 * tx + 1)      ? finf() : res[ii][1];
        float o2 = (ti == tj0 + 32 + 2 * tx)     ? finf() : res[ii][2];
        float o3 = (ti == tj0 + 32 + 2 * tx + 1) ? finf() : res[ii][3];
        *(float2*)(dr + 2 * tx)      = make_float2(o0, o1);
        *(float2*)(dr + 32 + 2 * tx) = make_float2(o2, o3);
    }

    if (x != y) {
        __syncthreads();
        float* tb = &As2[0][0][0];
#pragma unroll
        for (int ii = 0; ii < 4; ii++)
#pragma unroll
            for (int c = 0; c < 4; c++) {
                int col = (c >> 1) * 32 + 2 * tx + (c & 1);
                tb[(ty * 4 + ii) * 65 + col] = res[ii][c];
            }
        __syncthreads();

        int j  = t & 63;
        int ic = (t >> 6) * 16;
        if (tj0 + j < cnt) {
            float* drj = dq + (size_t)list[tj0 + j] * MAXC + ti0 + ic;
#pragma unroll
            for (int q = 0; q < 4; q++) {
                float4 o;
                o.x = tb[(ic + 4 * q + 0) * 65 + j];
                o.y = tb[(ic + 4 * q + 1) * 65 + j];
                o.z = tb[(ic + 4 * q + 2) * 65 + j];
                o.w = tb[(ic + 4 * q + 3) * 65 + j];
                *(float4*)(drj + 4 * q) = o;
            }
        }
    }
}

// ---------------------------------------------------------------------------
// Kernel 2: fused top-K + MSE + CE. TWO WARPS PER ROW (4096 warps -> 2x
// latency hiding): each warp selects top-20 of its 192-position half,
// both merge the 40 candidates redundantly, gather is split 10+10.
// Grid 512 x 256 (8 warps = 4 rows x 2 halves).
// ---------------------------------------------------------------------------
__device__ __forceinline__ unsigned tree_min6(const unsigned* v) {
    unsigned t0 = min(v[0], v[1]), t1 = min(v[2], v[3]), t2 = min(v[4], v[5]);
    return min(min(t0, t1), t2);
}

__global__ __launch_bounds__(256, 2)
void topk_loss_kernel(const float* __restrict__ feat,
                      const float* __restrict__ scores,
                      const int* __restrict__ target,
                      float* __restrict__ out) {
    __shared__ unsigned s_keys[4][2][20];   // phase-1 winners per row/half
    __shared__ float    s_rl[4][2];         // gather partials per row/half
    __shared__ float    s_rowpart[4];
    __shared__ bool     s_last;

    int warp = threadIdx.x >> 5;
    int lane = threadIdx.x & 31;
    int row  = warp >> 1;        // 0..3
    int h    = warp & 1;         // half
    int i = blockIdx.x * 4 + row;

    int cls = target[i];
    int cnt = min(g_cntC[cls], MAXC);
    const int* order = g_orderC + cls * MAXC;
    int m = min(cnt - 1, KSEL);

    // ---- phase 1: top-20 of this half's 192 positions ----
    int pbase = h * 192 + lane * 6;
    {
        const float* b0 = g_D + (size_t)i * MAXC + pbase;
        const float* b1 = g_D + (size_t)(N + i) * MAXC + pbase;
        const float* b2 = g_D + (size_t)(2 * N + i) * MAXC + pbase;
        const float* b3 = g_D + (size_t)(3 * N + i) * MAXC + pbase;

        float sum[6];
#pragma unroll
        for (int q = 0; q < 3; q++) {
            float2 a = *(const float2*)(b0 + 2 * q);
            float2 b = *(const float2*)(b1 + 2 * q);
            float2 c = *(const float2*)(b2 + 2 * q);
            float2 d = *(const float2*)(b3 + 2 * q);
            sum[2 * q + 0] = (a.x + b.x) + (c.x + d.x);
            sum[2 * q + 1] = (a.y + b.y) + (c.y + d.y);
        }

        unsigned v[6];
#pragma unroll
        for (int s = 0; s < 6; s++) {
            int p = pbase + s;
            v[s] = (p < cnt)
                 ? ((__float_as_uint(sum[s]) & 0xFFFFFE00u) | (unsigned)p)
                 : 0xFFFFFFFFu;
        }

        unsigned mykey = 0xFFFFFFFFu;
#pragma unroll
        for (int r = 0; r < 10; r++) {
            unsigned k1 = tree_min6(v);
            unsigned wv[6];
#pragma unroll
            for (int s = 0; s < 6; s++)
                wv[s] = (v[s] == k1) ? 0xFFFFFFFFu : v[s];
            unsigned k2 = tree_min6(wv);

            unsigned g1 = __reduce_min_sync(0xffffffffu, k1);
            unsigned cand = (k1 == g1) ? k2 : k1;
            unsigned g2 = __reduce_min_sync(0xffffffffu, cand);

            if (lane == 2 * r)     mykey = g1;
            if (lane == 2 * r + 1) mykey = g2;
#pragma unroll
            for (int s = 0; s < 6; s++) {
                if (v[s] == g1 || v[s] == g2) v[s] = 0xFFFFFFFFu;
            }
        }
        if (lane < 20) s_keys[row][h][lane] = mykey;
    }
    __syncthreads();

    // ---- phase 2: merge 40 candidates (both warps, redundant) ----
    unsigned mypos = 511u;
    {
        unsigned v2[2];
        v2[0] = (lane < 20) ? s_keys[row][0][lane] : 0xFFFFFFFFu;
        v2[1] = (lane < 20) ? s_keys[row][1][lane] : 0xFFFFFFFFu;
#pragma unroll
        for (int r = 0; r < 10; r++) {
            unsigned k1 = min(v2[0], v2[1]);
            unsigned k2 = max(v2[0], v2[1]);
            unsigned g1 = __reduce_min_sync(0xffffffffu, k1);
            unsigned cand = (k1 == g1) ? k2 : k1;
            unsigned g2 = __reduce_min_sync(0xffffffffu, cand);
            if (lane == 2 * r)     mypos = g1 & 511u;
            if (lane == 2 * r + 1) mypos = g2 & 511u;
            if (v2[0] == g1 || v2[0] == g2) v2[0] = 0xFFFFFFFFu;
            if (v2[1] == g1 || v2[1] == g2) v2[1] = 0xFFFFFFFFu;
        }
    }

    // resolve neighbor original index per lane (20 parallel loads)
    int myj = order[min(mypos, (unsigned)(MAXC - 1))];

    // ---- gather split: warp h covers k = 10h .. 10h+9 ----
    {
        float inv_m = 1.0f / (float)max(m, 1);
        const float* xi = feat + (size_t)i * C + lane * 8;
        float4 x0 = *(const float4*)(xi);
        float4 x1 = *(const float4*)(xi + 4);
        float acc = 0.f;
#pragma unroll
        for (int kk = 0; kk < 10; kk++) {
            int k = h * 10 + kk;
            bool valid = (k < m);
            int j = __shfl_sync(0xffffffffu, myj, k);
            const float* xj = feat + (size_t)j * C + lane * 8;
            float4 a0 = *(const float4*)(xj);
            float4 a1 = *(const float4*)(xj + 4);
            float s = 0.f, d;
            d = x0.x - a0.x * inv_m; s += d * d;
            d = x0.y - a0.y * inv_m; s += d * d;
            d = x0.z - a0.z * inv_m; s += d * d;
            d = x0.w - a0.w * inv_m; s += d * d;
            d = x1.x - a1.x * inv_m; s += d * d;
            d = x1.y - a1.y * inv_m; s += d * d;
            d = x1.z - a1.z * inv_m; s += d * d;
            d = x1.w - a1.w * inv_m; s += d * d;
            acc += valid ? s : 0.f;
        }
#pragma unroll
        for (int o = 16; o > 0; o >>= 1)
            acc += __shfl_down_sync(0xffffffffu, acc, o);
        if (lane == 0) s_rl[row][h] = acc;
    }
    __syncthreads();

    // ---- CE + row combine (warp h==0, lane 0) ----
    if (h == 0 && lane == 0) {
        float4 s0 = *(const float4*)(scores + (size_t)i * NCLS);
        float4 s1 = *(const float4*)(scores + (size_t)i * NCLS + 4);
        float sv[8] = {s0.x, s0.y, s0.z, s0.w, s1.x, s1.y, s1.z, s1.w};
        float mx = sv[0];
#pragma unroll
        for (int c = 1; c < 8; c++) mx = fmaxf(mx, sv[c]);
        float se = 0.f;
#pragma unroll
        for (int c = 0; c < 8; c++) se += __expf(sv[c] - mx);
        float ce = (mx + __logf(se)) - sv[cls];
        float rowloss = s_rl[row][0] + s_rl[row][1];
        s_rowpart[row] = ce * (1.0f / (float)N) + 25.0f * rowloss;  // LAM*0.5=25
    }
    __syncthreads();

    if (threadIdx.x == 0) {
        float p = s_rowpart[0] + s_rowpart[1] + s_rowpart[2] + s_rowpart[3];
        g_partial[blockIdx.x] = p;
        __threadfence();
        unsigned int done = atomicAdd(&g_counter, 1u);
        s_last = (done == 511u);
    }
    __syncthreads();

    if (s_last) {
        __shared__ float sred[256];
        int t = threadIdx.x;
        sred[t] = g_partial[t] + g_partial[256 + t];
        __syncthreads();
        for (int o = 128; o > 0; o >>= 1) {
            if (t < o) sred[t] += sred[t + o];
            __syncthreads();
        }
        if (t == 0) out[0] = sred[0];
    }
}

// ---------------------------------------------------------------------------
extern "C" void kernel_launch(void* const* d_in, const int* in_sizes, int n_in,
                              void* d_out, int out_size) {
    const float* feature = (const float*)d_in[0];   // [2048, 256]
    const float* scores  = (const float*)d_in[1];   // [2048, 8]
    const int*   target  = (const int*)d_in[2];     // [2048]
    float* out = (float*)d_out;

    dist_kernel<<<672, 256>>>(feature, target);
    topk_loss_kernel<<<N / 4, 256>>>(feature, scores, target, out);
}

// round 16
// speedup vs baseline: 1.1224x; 1.1224x over previous
#include <cuda_runtime.h>
#include <cuda_bf16.h>
#include <math.h>

// Problem shape (fixed by setup_inputs)
#define N     2048
#define C     256
#define NCLS  8
#define KSEL  20
#define MAXC  384      // class size bound; tiles cover 6*64=384
#define EPS   1e-6f

typedef unsigned long long u64;

// Scratch (static __device__ — no allocations)
// g_D layout: [4 channel-quarters][N rows (original index)][MAXC positions]
__device__ float g_D[4ull * N * MAXC];
__device__ int   g_orderC[NCLS * MAXC];   // per-class member lists (original indices)
__device__ int   g_cntC[NCLS];
__device__ float g_partial[512];
__device__ unsigned int g_counter;

// triangle tile enumeration: x >= y, 6x6 -> 21 tiles
__device__ __constant__ int c_tx[21] = {0,1,1,2,2,2,3,3,3,3,4,4,4,4,4,5,5,5,5,5,5};
__device__ __constant__ int c_ty[21] = {0,0,1,0,1,2,0,1,2,3,0,1,2,3,4,0,1,2,3,4,5};

__device__ __forceinline__ float finf() { return __int_as_float(0x7f800000); }

__device__ __forceinline__ u64 addx2(u64 a, u64 b) {
    u64 r;
    asm("add.rn.f32x2 %0, %1, %2;" : "=l"(r) : "l"(a), "l"(b));
    return r;
}

// ---------------------------------------------------------------------------
// Kernel 1: class-blocked pairwise L1 (no eps -> symmetric), channel-quarter
// split, TRIANGLE tiles only (x >= y), mirror store via smem transpose.
// Unchanged from R14 (measured ~18us).
// ---------------------------------------------------------------------------
#define TB 64
#define KC 64      // channels per chunk == quarter size (32 packed pairs)
#define PADTB 66   // padded row length (528 bytes, multiple of 16)

__global__ __launch_bounds__(256, 3)
void dist_kernel(const float* __restrict__ feat, const int* __restrict__ target) {
    int bid = blockIdx.x;
    if (bid == 0 && threadIdx.x == 0) g_counter = 0u;   // reset for topk

    int cs  = bid / 168;               // channel quarter 0..3
    int b   = bid - cs * 168;
    int cls = b / 21;
    int e   = b - cls * 21;
    int x = c_tx[e], y = c_ty[e];      // x >= y

    __shared__ __align__(16) float As2[KC / 2][PADTB][2];   // a, pair packed
    __shared__ __align__(16) float Bs2[KC / 2][PADTB][2];   // -b, pair packed
    __shared__ __align__(16) int   list[MAXC];
    __shared__ int   s_wofs[8];
    __shared__ int   s_cnt;

    int t    = threadIdx.x;
    int lane = t & 31;
    int w    = t >> 5;

    // ---- cheap count first: early-exit for non-working tiles ----
    int4 t0 = *(const int4*)(target + t * 8);
    int4 t1 = *(const int4*)(target + t * 8 + 4);
    int tg[8] = {t0.x, t0.y, t0.z, t0.w, t1.x, t1.y, t1.z, t1.w};
    int mcount = 0;
#pragma unroll
    for (int u = 0; u < 8; u++) mcount += (tg[u] == cls);

    int red = mcount;
#pragma unroll
    for (int o = 16; o > 0; o >>= 1) red += __shfl_down_sync(0xffffffffu, red, o);
    if (lane == 0) s_wofs[w] = red;
    __syncthreads();
    if (t == 0) {
        int acc = 0;
#pragma unroll
        for (int ww = 0; ww < 8; ww++) acc += s_wofs[ww];
        s_cnt = acc;
    }
    __syncthreads();
    int cnt = min(s_cnt, MAXC);

    int ti0 = y * TB;
    int tj0 = x * TB;
    if (ti0 >= cnt || tj0 >= cnt) return;   // publishers (e==0) always pass

    // ---- full stable compaction (working blocks only) ----
    int incl = mcount;
#pragma unroll
    for (int o = 1; o < 32; o <<= 1) {
        int v = __shfl_up_sync(0xffffffffu, incl, o);
        if (lane >= o) incl += v;
    }
    if (lane == 31) s_wofs[w] = incl;
    __syncthreads();
    if (t == 0) {
        int acc = 0;
#pragma unroll
        for (int ww = 0; ww < 8; ww++) { int v = s_wofs[ww]; s_wofs[ww] = acc; acc += v; }
    }
    __syncthreads();
    int base = s_wofs[w] + incl - mcount;   // exclusive prefix for this thread
#pragma unroll
    for (int u = 0; u < 8; u++) {
        if (tg[u] == cls && base < MAXC) { list[base] = t * 8 + u; base++; }
    }
    __syncthreads();
    for (int p = cnt + t; p < MAXC; p += 256) list[p] = 0;   // safe padding
    __syncthreads();

    // publisher blocks export the list for topk (one block per class)
    if (cs == 0 && e == 0) {
        if (t == 0) g_cntC[cls] = cnt;
        for (int p = t; p < MAXC; p += 256) g_orderC[cls * MAXC + p] = list[p];
    }

    // ---- staging: thread t fills column lr, 16 channels ----
    {
        int lr = t & 63;
        int lc = (t >> 6) * 16;       // 0,16,32,48
        int gi = ti0 + lr, gj = tj0 + lr;
        const float* arow = feat + (size_t)list[min(gi, MAXC - 1)] * C;
        const float* brow = feat + (size_t)list[min(gj, MAXC - 1)] * C;
        int cc = cs * 64 + lc;
        int p0 = lc >> 1;
#pragma unroll
        for (int q = 0; q < 4; q++) {
            float4 pa = *(const float4*)(arow + cc + q * 4);
            float4 pb = *(const float4*)(brow + cc + q * 4);
            *(float2*)&As2[p0 + 2 * q + 0][lr][0] = make_float2(pa.x, pa.y);
            *(float2*)&As2[p0 + 2 * q + 1][lr][0] = make_float2(pa.z, pa.w);
            *(float2*)&Bs2[p0 + 2 * q + 0][lr][0] = make_float2(-pb.x, -pb.y);
            *(float2*)&Bs2[p0 + 2 * q + 1][lr][0] = make_float2(-pb.z, -pb.w);
        }
    }
    __syncthreads();

    int tx = t & 15;      // j columns: {2tx, 2tx+1, 32+2tx, 32+2tx+1}
    int ty = t >> 4;      // i rows: ty*4 + ii

    u64 acc2[16];
#pragma unroll
    for (int q = 0; q < 16; q++) acc2[q] = 0ull;

#pragma unroll
    for (int kk2 = 0; kk2 < KC / 2; kk2++) {
        ulonglong2 aL = *(const ulonglong2*)&As2[kk2][ty * 4][0];
        ulonglong2 aH = *(const ulonglong2*)&As2[kk2][ty * 4 + 2][0];
        u64 a2[4] = {aL.x, aL.y, aH.x, aH.y};
        ulonglong2 bL = *(const ulonglong2*)&Bs2[kk2][2 * tx][0];
        ulonglong2 bH = *(const ulonglong2*)&Bs2[kk2][32 + 2 * tx][0];
        u64 b2[4] = {bL.x, bL.y, bH.x, bH.y};
#pragma unroll
        for (int ii = 0; ii < 4; ii++)
#pragma unroll
            for (int c = 0; c < 4; c++) {
                u64 d = addx2(a2[ii], b2[c]);           // a - b
                d &= 0x7FFFFFFF7FFFFFFFull;             // packed |.|
                acc2[ii * 4 + c] = addx2(acc2[ii * 4 + c], d);
            }
    }

    float res[4][4];
#pragma unroll
    for (int ii = 0; ii < 4; ii++)
#pragma unroll
        for (int c = 0; c < 4; c++) {
            u64 a = acc2[ii * 4 + c];
            float lo = __uint_as_float((unsigned)(a & 0xFFFFFFFFull));
            float hi = __uint_as_float((unsigned)(a >> 32));
            res[ii][c] = lo + hi;
        }

    float* dq = g_D + (size_t)cs * N * MAXC;

#pragma unroll
    for (int ii = 0; ii < 4; ii++) {
        int ti = ti0 + ty * 4 + ii;
        if (ti >= cnt) continue;
        float* dr = dq + (size_t)list[ti] * MAXC + tj0;
        float o0 = (ti == tj0 + 2 * tx)          ? finf() : res[ii][0];
        float o1 = (ti == tj0 + 2 * tx + 1)      ? finf() : res[ii][1];
        float o2 = (ti == tj0 + 32 + 2 * tx)     ? finf() : res[ii][2];
        float o3 = (ti == tj0 + 32 + 2 * tx + 1) ? finf() : res[ii][3];
        *(float2*)(dr + 2 * tx)      = make_float2(o0, o1);
        *(float2*)(dr + 32 + 2 * tx) = make_float2(o2, o3);
    }

    if (x != y) {
        __syncthreads();
        float* tb = &As2[0][0][0];
#pragma unroll
        for (int ii = 0; ii < 4; ii++)
#pragma unroll
            for (int c = 0; c < 4; c++) {
                int col = (c >> 1) * 32 + 2 * tx + (c & 1);
                tb[(ty * 4 + ii) * 65 + col] = res[ii][c];
            }
        __syncthreads();

        int j  = t & 63;
        int ic = (t >> 6) * 16;
        if (tj0 + j < cnt) {
            float* drj = dq + (size_t)list[tj0 + j] * MAXC + ti0 + ic;
#pragma unroll
            for (int q = 0; q < 4; q++) {
                float4 o;
                o.x = tb[(ic + 4 * q + 0) * 65 + j];
                o.y = tb[(ic + 4 * q + 1) * 65 + j];
                o.z = tb[(ic + 4 * q + 2) * 65 + j];
                o.w = tb[(ic + 4 * q + 3) * 65 + j];
                *(float4*)(drj + 4 * q) = o;
            }
        }
    }
}

// ---------------------------------------------------------------------------
// Kernel 2: fused top-K + MSE + CE. Two warps per row (4096 warps), NOW with
// __launch_bounds__(256,4) -> 64-reg cap -> 32 warps/SM occupancy ceiling,
// so the doubled parallelism is actually resident.
// ---------------------------------------------------------------------------
__device__ __forceinline__ unsigned tree_min6(const unsigned* v) {
    unsigned t0 = min(v[0], v[1]), t1 = min(v[2], v[3]), t2 = min(v[4], v[5]);
    return min(min(t0, t1), t2);
}

__global__ __launch_bounds__(256, 4)
void topk_loss_kernel(const float* __restrict__ feat,
                      const float* __restrict__ scores,
                      const int* __restrict__ target,
                      float* __restrict__ out) {
    __shared__ unsigned s_keys[4][2][20];   // phase-1 winners per row/half
    __shared__ float    s_rl[4][2];         // gather partials per row/half
    __shared__ float    s_rowpart[4];
    __shared__ bool     s_last;

    int warp = threadIdx.x >> 5;
    int lane = threadIdx.x & 31;
    int row  = warp >> 1;        // 0..3
    int h    = warp & 1;         // half
    int i = blockIdx.x * 4 + row;

    int cls = target[i];
    int cnt = min(g_cntC[cls], MAXC);
    const int* order = g_orderC + cls * MAXC;
    int m = min(cnt - 1, KSEL);

    // ---- phase 1: top-20 of this half's 192 positions ----
    int pbase = h * 192 + lane * 6;
    {
        const float* b0 = g_D + (size_t)i * MAXC + pbase;
        const float* b1 = g_D + (size_t)(N + i) * MAXC + pbase;
        const float* b2 = g_D + (size_t)(2 * N + i) * MAXC + pbase;
        const float* b3 = g_D + (size_t)(3 * N + i) * MAXC + pbase;

        float sum[6];
#pragma unroll
        for (int q = 0; q < 3; q++) {
            float2 a = *(const float2*)(b0 + 2 * q);
            float2 b = *(const float2*)(b1 + 2 * q);
            float2 c = *(const float2*)(b2 + 2 * q);
            float2 d = *(const float2*)(b3 + 2 * q);
            sum[2 * q + 0] = (a.x + b.x) + (c.x + d.x);
            sum[2 * q + 1] = (a.y + b.y) + (c.y + d.y);
        }

        unsigned v[6];
#pragma unroll
        for (int s = 0; s < 6; s++) {
            int p = pbase + s;
            v[s] = (p < cnt)
                 ? ((__float_as_uint(sum[s]) & 0xFFFFFE00u) | (unsigned)p)
                 : 0xFFFFFFFFu;
        }

        unsigned mykey = 0xFFFFFFFFu;
#pragma unroll
        for (int r = 0; r < 10; r++) {
            unsigned k1 = tree_min6(v);
            unsigned wv[6];
#pragma unroll
            for (int s = 0; s < 6; s++)
                wv[s] = (v[s] == k1) ? 0xFFFFFFFFu : v[s];
            unsigned k2 = tree_min6(wv);

            unsigned g1 = __reduce_min_sync(0xffffffffu, k1);
            unsigned cand = (k1 == g1) ? k2 : k1;
            unsigned g2 = __reduce_min_sync(0xffffffffu, cand);

            if (lane == 2 * r)     mykey = g1;
            if (lane == 2 * r + 1) mykey = g2;
#pragma unroll
            for (int s = 0; s < 6; s++) {
                if (v[s] == g1 || v[s] == g2) v[s] = 0xFFFFFFFFu;
            }
        }
        if (lane < 20) s_keys[row][h][lane] = mykey;
    }
    __syncthreads();

    // ---- phase 2: merge 40 candidates (both warps, redundant) ----
    unsigned mypos = 511u;
    {
        unsigned v2[2];
        v2[0] = (lane < 20) ? s_keys[row][0][lane] : 0xFFFFFFFFu;
        v2[1] = (lane < 20) ? s_keys[row][1][lane] : 0xFFFFFFFFu;
#pragma unroll
        for (int r = 0; r < 10; r++) {
            unsigned k1 = min(v2[0], v2[1]);
            unsigned k2 = max(v2[0], v2[1]);
            unsigned g1 = __reduce_min_sync(0xffffffffu, k1);
            unsigned cand = (k1 == g1) ? k2 : k1;
            unsigned g2 = __reduce_min_sync(0xffffffffu, cand);
            if (lane == 2 * r)     mypos = g1 & 511u;
            if (lane == 2 * r + 1) mypos = g2 & 511u;
            if (v2[0] == g1 || v2[0] == g2) v2[0] = 0xFFFFFFFFu;
            if (v2[1] == g1 || v2[1] == g2) v2[1] = 0xFFFFFFFFu;
        }
    }

    // resolve neighbor original index per lane (20 parallel loads)
    int myj = order[min(mypos, (unsigned)(MAXC - 1))];

    // ---- gather split: warp h covers k = 10h .. 10h+9 ----
    {
        float inv_m = 1.0f / (float)max(m, 1);
        const float* xi = feat + (size_t)i * C + lane * 8;
        float4 x0 = *(const float4*)(xi);
        float4 x1 = *(const float4*)(xi + 4);
        float acc = 0.f;
#pragma unroll
        for (int kk = 0; kk < 10; kk++) {
            int k = h * 10 + kk;
            bool valid = (k < m);
            int j = __shfl_sync(0xffffffffu, myj, k);
            const float* xj = feat + (size_t)j * C + lane * 8;
            float4 a0 = *(const float4*)(xj);
            float4 a1 = *(const float4*)(xj + 4);
            float s = 0.f, d;
            d = x0.x - a0.x * inv_m; s += d * d;
            d = x0.y - a0.y * inv_m; s += d * d;
            d = x0.z - a0.z * inv_m; s += d * d;
            d = x0.w - a0.w * inv_m; s += d * d;
            d = x1.x - a1.x * inv_m; s += d * d;
            d = x1.y - a1.y * inv_m; s += d * d;
            d = x1.z - a1.z * inv_m; s += d * d;
            d = x1.w - a1.w * inv_m; s += d * d;
            acc += valid ? s : 0.f;
        }
#pragma unroll
        for (int o = 16; o > 0; o >>= 1)
            acc += __shfl_down_sync(0xffffffffu, acc, o);
        if (lane == 0) s_rl[row][h] = acc;
    }
    __syncthreads();

    // ---- CE + row combine (warp h==0, lane 0) ----
    if (h == 0 && lane == 0) {
        float4 s0 = *(const float4*)(scores + (size_t)i * NCLS);
        float4 s1 = *(const float4*)(scores + (size_t)i * NCLS + 4);
        float sv[8] = {s0.x, s0.y, s0.z, s0.w, s1.x, s1.y, s1.z, s1.w};
        float mx = sv[0];
#pragma unroll
        for (int c = 1; c < 8; c++) mx = fmaxf(mx, sv[c]);
        float se = 0.f;
#pragma unroll
        for (int c = 0; c < 8; c++) se += __expf(sv[c] - mx);
        float ce = (mx + __logf(se)) - sv[cls];
        float rowloss = s_rl[row][0] + s_rl[row][1];
        s_rowpart[row] = ce * (1.0f / (float)N) + 25.0f * rowloss;  // LAM*0.5=25
    }
    __syncthreads();

    if (threadIdx.x == 0) {
        float p = s_rowpart[0] + s_rowpart[1] + s_rowpart[2] + s_rowpart[3];
        g_partial[blockIdx.x] = p;
        __threadfence();
        unsigned int done = atomicAdd(&g_counter, 1u);
        s_last = (done == 511u);
    }
    __syncthreads();

    if (s_last) {
        __shared__ float sred[256];
        int t = threadIdx.x;
        sred[t] = g_partial[t] + g_partial[256 + t];
        __syncthreads();
        for (int o = 128; o > 0; o >>= 1) {
            if (t < o) sred[t] += sred[t + o];
            __syncthreads();
        }
        if (t == 0) out[0] = sred[0];
    }
}

// ---------------------------------------------------------------------------
extern "C" void kernel_launch(void* const* d_in, const int* in_sizes, int n_in,
                              void* d_out, int out_size) {
    const float* feature = (const float*)d_in[0];   // [2048, 256]
    const float* scores  = (const float*)d_in[1];   // [2048, 8]
    const int*   target  = (const int*)d_in[2];     // [2048]
    float* out = (float*)d_out;

    dist_kernel<<<672, 256>>>(feature, target);
    topk_loss_kernel<<<N / 4, 256>>>(feature, scores, target, out);
}